// round 10
// baseline (speedup 1.0000x reference)
#include <cuda_runtime.h>
#include <math.h>
#include <cstdint>

#define T    4096
#define S    256
#define NCTA 16       // non-portable cluster size (fits in one GPC on B300)
#define WPC  16       // warps per CTA -> NCTA*WPC == S rows
#define NB   64       // backtrace chunks
#define CH   64       // steps per chunk (NB*CH == T)

// ---- device scratch (no cudaMalloc allowed) ----
__device__ int g_bp[T * S];       // backpointers (filled by sv_bp post-pass)
__device__ int g_link[NB][S];     // composed chunk maps

__device__ __forceinline__ uint32_t smem_u32(const void* p) {
    uint32_t a;
    asm("{ .reg .u64 t; cvta.to.shared.u64 t, %1; cvt.u32.u64 %0, t; }"
        : "=r"(a) : "l"(p));
    return a;
}
__device__ __forceinline__ uint32_t ctarank() {
    uint32_t r;
    asm("mov.u32 %0, %%cluster_ctarank;" : "=r"(r));
    return r;
}
__device__ __forceinline__ uint32_t mapa_u32(uint32_t addr, uint32_t rank) {
    uint32_t rem;
    asm("mapa.shared::cluster.u32 %0, %1, %2;" : "=r"(rem) : "r"(addr), "r"(rank));
    return rem;
}
// wait until the local mbarrier completes the phase with the given parity
__device__ __forceinline__ void mbar_wait_cluster(uint32_t mbar, uint32_t parity) {
    uint32_t done;
    asm volatile(
        "{ .reg .pred p;\n\t"
        "mbarrier.try_wait.parity.acquire.cluster.shared::cta.b64 p, [%1], %2;\n\t"
        "selp.b32 %0, 1, 0, p; }"
        : "=r"(done) : "r"(mbar), "r"(parity) : "memory");
    if (!done) {
        asm volatile(
            "{ .reg .pred P1;\n\t"
            "WAIT_%=:\n\t"
            "mbarrier.try_wait.parity.acquire.cluster.shared::cta.b64 P1, [%0], %1, 0x989680;\n\t"
            "@P1 bra.uni DONE_%=;\n\t"
            "bra.uni WAIT_%=;\n\t"
            "DONE_%=: }"
            :: "r"(mbar), "r"(parity) : "memory");
    }
}

// ============ sequential DP: LSE only, no argmax ============
__global__ __launch_bounds__(512, 1) __cluster_dims__(NCTA, 1, 1)
void sv_dp(const float* __restrict__ pot, float* __restrict__ out) {
    __shared__ float vbuf[2][S];              // double-buffered v, full copy per CTA
    __shared__ alignas(8) unsigned long long mbar[2];

    const int tid  = threadIdx.x;
    const int w    = tid >> 5;
    const int lane = tid & 31;
    const uint32_t rank = ctarank();
    const int s    = (int)rank * WPC + w;     // state row owned by this warp
    float* vout = out + T;                    // v[t*S + s]

    const uint32_t mb0 = smem_u32(&mbar[0]);
    const uint32_t mb1 = smem_u32(&mbar[1]);

    if (tid == 0) {
        asm volatile("mbarrier.init.shared.b64 [%0], %1;" :: "r"(mb0), "r"(NCTA) : "memory");
        asm volatile("mbarrier.init.shared.b64 [%0], %1;" :: "r"(mb1), "r"(NCTA) : "memory");
    }
    // v0 = pot[0,0,:]: every CTA fills its local copy; CTA 0 also writes output
    if (tid < S) {
        vbuf[0][tid] = pot[tid];
        if (rank == 0) vout[tid] = pot[tid];
    }
    __syncthreads();
    // make mbarrier inits visible cluster-wide before any remote arrive
    asm volatile("barrier.cluster.arrive.aligned;" ::: "memory");
    asm volatile("barrier.cluster.wait.aligned;" ::: "memory");

    const float* prow = pot + (size_t)s * S;
    const int c0 = 4 * lane;          // columns c0..c0+3
    const int c1 = 128 + 4 * lane;    // columns c1..c1+3

    float K = pot[s];                 // K-shift base (own previous v)

    // precomputed remote addresses (per-lane): v slots and mbarriers at rank=lane
    uint32_t rem_s0 = 0, rem_s1 = 0, rem_m0 = 0, rem_m1 = 0;
    if (lane < NCTA) {
        rem_s0 = mapa_u32(smem_u32(&vbuf[0][s]), (uint32_t)lane);
        rem_s1 = mapa_u32(smem_u32(&vbuf[1][s]), (uint32_t)lane);
        rem_m0 = mapa_u32(mb0, (uint32_t)lane);
        rem_m1 = mapa_u32(mb1, (uint32_t)lane);
    }

    // prefetch pot for t = 1
    float4 pA = *(const float4*)(prow + (size_t)S * S + c0);
    float4 pB = *(const float4*)(prow + (size_t)S * S + c1);

    for (int t = 1; t < T; ++t) {
        // prefetch for t+1 (lands during wait/compute)
        const size_t nxt = (size_t)((t + 1 < T) ? (t + 1) : t) * S * S;
        float4 nA = *(const float4*)(prow + nxt + c0);
        float4 nB = *(const float4*)(prow + nxt + c1);

        // wait for publication t-1 (mbar[(t-1)&1], parity ((t-2)>>1)&1); t==1 needs none
        if (t > 1)
            mbar_wait_cluster(((t - 1) & 1) ? mb1 : mb0, (uint32_t)(((t - 2) >> 1) & 1));

        // read v_{t-1} from LOCAL smem
        const float* vp = vbuf[(t - 1) & 1];
        float4 vA = *(const float4*)(vp + c0);
        float4 vB = *(const float4*)(vp + c1);

        // exps start immediately (K-shift: no max dependency)
        float e = __expf(vA.x + pA.x - K) + __expf(vA.y + pA.y - K) +
                  __expf(vA.z + pA.z - K) + __expf(vA.w + pA.w - K) +
                  __expf(vB.x + pB.x - K) + __expf(vB.y + pB.y - K) +
                  __expf(vB.z + pB.z - K) + __expf(vB.w + pB.w - K);

        // sum-only tree
        #pragma unroll
        for (int o = 16; o; o >>= 1)
            e += __shfl_xor_sync(0xffffffffu, e, o);

        float v = K + __logf(e);      // all lanes have v

        // publish v_t[s] into all 16 CTAs' smem (lanes 0..15, one rank each)
        if (lane < NCTA) {
            asm volatile("st.shared::cluster.f32 [%0], %1;"
                         :: "r"((t & 1) ? rem_s1 : rem_s0), "f"(v) : "memory");
        }
        if (lane == 0) vout[(size_t)t * S + s] = v;

        // all local warps' remote stores done -> fence -> aggregate-arrive everywhere
        __syncthreads();
        if (w == 0) {
            if (lane == 0)
                asm volatile("fence.acq_rel.cluster;" ::: "memory");
            __syncwarp();
            if (lane < NCTA)
                asm volatile("mbarrier.arrive.release.cluster.shared::cluster.b64 _, [%0];"
                             :: "r"((t & 1) ? rem_m1 : rem_m0) : "memory");
        }

        K = v;
        pA = nA; pB = nB;
    }

    // no CTA may exit while peers might still store/arrive into its SMEM
    asm volatile("barrier.cluster.arrive.aligned;" ::: "memory");
    asm volatile("barrier.cluster.wait.aligned;" ::: "memory");
}

// ============ parallel backpointer recompute ============
// bp[t][s] = argmax_{s'} (v[t-1][s'] + pot[t][s][s']), first-index tie-break
__global__ __launch_bounds__(256, 4)
void sv_bp(const float* __restrict__ pot, const float* __restrict__ out) {
    __shared__ float vprev[S];
    const int t    = (int)blockIdx.x + 1;
    const int tid  = threadIdx.x;
    const int w    = tid >> 5;
    const int lane = tid & 31;
    const float* vout = out + T;

    if (tid < S)
        vprev[tid] = (t == 1) ? pot[tid] : vout[(size_t)(t - 1) * S + tid];
    __syncthreads();

    const int c0 = 4 * lane;
    const int c1 = 128 + 4 * lane;
    float4 vA = *(const float4*)(vprev + c0);
    float4 vB = *(const float4*)(vprev + c1);

    for (int r = 0; r < 32; ++r) {
        const int s = w * 32 + r;
        const float* prow = pot + (size_t)t * S * S + (size_t)s * S;
        float4 pA = *(const float4*)(prow + c0);
        float4 pB = *(const float4*)(prow + c1);

        float sc[8];
        sc[0] = vA.x + pA.x;  sc[1] = vA.y + pA.y;
        sc[2] = vA.z + pA.z;  sc[3] = vA.w + pA.w;
        sc[4] = vB.x + pB.x;  sc[5] = vB.y + pB.y;
        sc[6] = vB.z + pB.z;  sc[7] = vB.w + pB.w;

        float m = sc[0]; int mi = c0;
        #pragma unroll
        for (int k = 1; k < 8; ++k) {
            int c = (k < 4) ? (c0 + k) : (c1 + (k - 4));
            if (sc[k] > m) { m = sc[k]; mi = c; }
        }
        #pragma unroll
        for (int o = 16; o; o >>= 1) {
            float om = __shfl_xor_sync(0xffffffffu, m, o);
            int   oi = __shfl_xor_sync(0xffffffffu, mi, o);
            if (om > m || (om == m && oi < mi)) { m = om; mi = oi; }
        }
        if (lane == 0) g_bp[t * S + s] = mi;
    }
}

// compose each chunk's backpointer map
__global__ void sv_link() {
    int b = blockIdx.x;
    if (b == 0) return;
    int cur = threadIdx.x;
    int tlo = b * CH;
    for (int t = tlo + CH - 2; t >= tlo - 1; --t)
        cur = g_bp[(t + 1) * S + cur];
    g_link[b][threadIdx.x] = cur;
}

__global__ void sv_back(float* __restrict__ out) {
    __shared__ float sm[8];
    __shared__ int   si[8];
    __shared__ int   sE[NB];
    const int tid = threadIdx.x, lane = tid & 31;

    const float* vlast = out + T + (size_t)(T - 1) * S;
    float m = vlast[tid]; int mi = tid;
    #pragma unroll
    for (int o = 16; o; o >>= 1) {
        float om = __shfl_xor_sync(0xffffffffu, m, o);
        int   oi = __shfl_xor_sync(0xffffffffu, mi, o);
        if (om > m || (om == m && oi < mi)) { m = om; mi = oi; }
    }
    if (lane == 0) { sm[tid >> 5] = m; si[tid >> 5] = mi; }
    __syncthreads();

    if (tid == 0) {
        m = sm[0]; mi = si[0];
        #pragma unroll
        for (int w = 1; w < 8; ++w)
            if (sm[w] > m || (sm[w] == m && si[w] < mi)) { m = sm[w]; mi = si[w]; }
        int e = mi;
        sE[NB - 1] = e;
        for (int b = NB - 1; b >= 1; --b) { e = g_link[b][e]; sE[b - 1] = e; }
    }
    __syncthreads();

    if (tid < NB) {
        int b = tid;
        int cur = sE[b];
        out[b * CH + CH - 1] = (float)cur;
        for (int t = b * CH + CH - 2; t >= b * CH; --t) {
            cur = g_bp[(t + 1) * S + cur];
            out[t] = (float)cur;
        }
    }
}

extern "C" void kernel_launch(void* const* d_in, const int* in_sizes, int n_in,
                              void* d_out, int out_size) {
    const float* pot = (const float*)d_in[0];
    float* out = (float*)d_out;

    // allow the 16-CTA non-portable cluster (idempotent, capture-legal)
    cudaFuncSetAttribute(sv_dp, cudaFuncAttributeNonPortableClusterSizeAllowed, 1);

    sv_dp<<<NCTA, 512>>>(pot, out);
    sv_bp<<<T - 1, 256>>>(pot, out);
    sv_link<<<NB, 256>>>();
    sv_back<<<1, 256>>>(out);
}

// round 11
// speedup vs baseline: 1.8648x; 1.8648x over previous
#include <cuda_runtime.h>
#include <math.h>
#include <cstdint>

#define T    4096
#define S    256
#define NCTA 16       // non-portable cluster size (fits in one GPC on B300)
#define WPC  16       // warps per CTA -> NCTA*WPC == S rows
#define D    8        // publication ring depth (buffers)
#define BP   7        // cluster barrier period (must be <= D-1 for safety proof)
#define NB   64       // backtrace chunks
#define CH   64       // steps per chunk (NB*CH == T)

// ---- device scratch (no cudaMalloc allowed) ----
__device__ int g_bp[T * S];       // backpointers (filled by sv_bp post-pass)
__device__ int g_link[NB][S];     // composed chunk maps

__device__ __forceinline__ uint32_t smem_u32(const void* p) {
    uint32_t a;
    asm("{ .reg .u64 t; cvta.to.shared.u64 t, %1; cvt.u32.u64 %0, t; }"
        : "=r"(a) : "l"(p));
    return a;
}
__device__ __forceinline__ uint32_t ctarank() {
    uint32_t r;
    asm("mov.u32 %0, %%cluster_ctarank;" : "=r"(r));
    return r;
}
__device__ __forceinline__ uint32_t mapa_u32(uint32_t addr, uint32_t rank) {
    uint32_t rem;
    asm("mapa.shared::cluster.u32 %0, %1, %2;" : "=r"(rem) : "r"(addr), "r"(rank));
    return rem;
}
__device__ __forceinline__ void lds_v2_vol(uint32_t addr,
                                           unsigned long long& a, unsigned long long& b) {
    asm volatile("ld.volatile.shared.v2.u64 {%0,%1}, [%2];"
                 : "=l"(a), "=l"(b) : "r"(addr));
}
__device__ __forceinline__ void st_cluster_u64(uint32_t addr, unsigned long long v) {
    asm volatile("st.shared::cluster.u64 [%0], %1;" :: "r"(addr), "l"(v) : "memory");
}

// ============ sequential DP: LSE only, tagged-word publication ============
__global__ __launch_bounds__(512, 1) __cluster_dims__(NCTA, 1, 1)
void sv_dp(const float* __restrict__ pot, float* __restrict__ out) {
    // ring of tagged v buffers: (tag<<32)|f32bits, one full copy per CTA
    __shared__ alignas(16) unsigned long long vbuf[D][S];

    const int tid  = threadIdx.x;
    const int w    = tid >> 5;
    const int lane = tid & 31;
    const uint32_t rank = ctarank();
    const int s    = (int)rank * WPC + w;     // state row owned by this warp
    float* vout = out + T;                    // v[t*S + s]

    // init all tags to invalid
    for (int i = tid; i < D * S; i += 512)
        ((unsigned long long*)vbuf)[i] = ~0ULL;
    if (rank == 0 && tid < S) vout[tid] = pot[tid];   // v0 row of output
    __syncthreads();
    // all CTAs' rings initialized before any remote store may land
    asm volatile("barrier.cluster.arrive.aligned;" ::: "memory");
    asm volatile("barrier.cluster.wait.aligned;" ::: "memory");

    const float* prow = pot + (size_t)s * S;
    const int c0 = 4 * lane;          // columns c0..c0+3
    const int c1 = 128 + 4 * lane;    // columns c1..c1+3

    float K = pot[s];                 // K-shift base = own previous v

    // remote base address of ring slot [0][s] in CTA 'lane'
    uint32_t rem_base = 0;
    if (lane < NCTA)
        rem_base = mapa_u32(smem_u32(&vbuf[0][s]), (uint32_t)lane);
    // local poll base addresses for this lane's 4 vector loads
    const uint32_t lb = smem_u32(&vbuf[0][0]);
    const uint32_t la0 = lb + (uint32_t)c0 * 8u;
    const uint32_t la1 = lb + (uint32_t)(c0 + 2) * 8u;
    const uint32_t la2 = lb + (uint32_t)c1 * 8u;
    const uint32_t la3 = lb + (uint32_t)(c1 + 2) * 8u;

    // publish v0 (tag 0) into all CTAs' ring slot 0
    if (lane < NCTA)
        st_cluster_u64(rem_base, (unsigned long long)__float_as_uint(K));

    // prefetch pot for t = 1
    float4 pA = *(const float4*)(prow + (size_t)S * S + c0);
    float4 pB = *(const float4*)(prow + (size_t)S * S + c1);

    int bc = 0;
    for (int t = 1; t < T; ++t) {
        // prefetch for t+1 (lands during poll/compute)
        const size_t nxt = (size_t)((t + 1 < T) ? (t + 1) : t) * S * S;
        float4 nA = *(const float4*)(prow + nxt + c0);
        float4 nB = *(const float4*)(prow + nxt + c1);

        // poll local ring slot (t-1)&7 until all 8 tags == t-1
        const uint32_t bo = (uint32_t)((t - 1) & (D - 1)) * (S * 8u);
        const unsigned tg = (unsigned)(t - 1);
        unsigned long long a0, a1, a2, a3, b0, b1, b2, b3;
        for (;;) {
            lds_v2_vol(la0 + bo, a0, a1);
            lds_v2_vol(la1 + bo, a2, a3);
            lds_v2_vol(la2 + bo, b0, b1);
            lds_v2_vol(la3 + bo, b2, b3);
            bool ok = ((unsigned)(a0 >> 32) == tg) & ((unsigned)(a1 >> 32) == tg) &
                      ((unsigned)(a2 >> 32) == tg) & ((unsigned)(a3 >> 32) == tg) &
                      ((unsigned)(b0 >> 32) == tg) & ((unsigned)(b1 >> 32) == tg) &
                      ((unsigned)(b2 >> 32) == tg) & ((unsigned)(b3 >> 32) == tg);
            if (__all_sync(0xffffffffu, ok)) break;
        }

        // scores and exps (K-shift: no max dependency)
        float e = __expf(__uint_as_float((unsigned)a0) + pA.x - K) +
                  __expf(__uint_as_float((unsigned)a1) + pA.y - K) +
                  __expf(__uint_as_float((unsigned)a2) + pA.z - K) +
                  __expf(__uint_as_float((unsigned)a3) + pA.w - K) +
                  __expf(__uint_as_float((unsigned)b0) + pB.x - K) +
                  __expf(__uint_as_float((unsigned)b1) + pB.y - K) +
                  __expf(__uint_as_float((unsigned)b2) + pB.z - K) +
                  __expf(__uint_as_float((unsigned)b3) + pB.w - K);

        // sum-only tree
        #pragma unroll
        for (int o = 16; o; o >>= 1)
            e += __shfl_xor_sync(0xffffffffu, e, o);

        float v = K + __logf(e);      // all lanes have v

        // publish v_t[s] into all 16 CTAs' ring slot t&7 (single 8B atom: tag+value)
        const unsigned long long pack =
            ((unsigned long long)(unsigned)t << 32) |
            (unsigned long long)__float_as_uint(v);
        if (lane < NCTA)
            st_cluster_u64(rem_base + (uint32_t)(t & (D - 1)) * (S * 8u), pack);
        if (lane == 0) vout[(size_t)t * S + s] = v;

        // ring-safety barrier every BP steps (proof: barrier after publishing B
        // => all consumed B-1 => slots for steps <= B-1 reusable through B+7)
        if (++bc == BP) {
            asm volatile("barrier.cluster.arrive.aligned;" ::: "memory");
            asm volatile("barrier.cluster.wait.aligned;" ::: "memory");
            bc = 0;
        }

        K = v;
        pA = nA; pB = nB;
    }

    // no CTA may exit while peers might still store into its SMEM
    asm volatile("barrier.cluster.arrive.aligned;" ::: "memory");
    asm volatile("barrier.cluster.wait.aligned;" ::: "memory");
}

// ============ parallel backpointer recompute ============
// bp[t][s] = argmax_{s'} (v[t-1][s'] + pot[t][s][s']), first-index tie-break
__global__ __launch_bounds__(256, 4)
void sv_bp(const float* __restrict__ pot, const float* __restrict__ out) {
    __shared__ float vprev[S];
    const int t    = (int)blockIdx.x + 1;
    const int tid  = threadIdx.x;
    const int w    = tid >> 5;
    const int lane = tid & 31;
    const float* vout = out + T;

    if (tid < S)
        vprev[tid] = (t == 1) ? pot[tid] : vout[(size_t)(t - 1) * S + tid];
    __syncthreads();

    const int c0 = 4 * lane;
    const int c1 = 128 + 4 * lane;
    float4 vA = *(const float4*)(vprev + c0);
    float4 vB = *(const float4*)(vprev + c1);

    for (int r = 0; r < 32; ++r) {
        const int s = w * 32 + r;
        const float* prow = pot + (size_t)t * S * S + (size_t)s * S;
        float4 pA = *(const float4*)(prow + c0);
        float4 pB = *(const float4*)(prow + c1);

        float sc[8];
        sc[0] = vA.x + pA.x;  sc[1] = vA.y + pA.y;
        sc[2] = vA.z + pA.z;  sc[3] = vA.w + pA.w;
        sc[4] = vB.x + pB.x;  sc[5] = vB.y + pB.y;
        sc[6] = vB.z + pB.z;  sc[7] = vB.w + pB.w;

        float m = sc[0]; int mi = c0;
        #pragma unroll
        for (int k = 1; k < 8; ++k) {
            int c = (k < 4) ? (c0 + k) : (c1 + (k - 4));
            if (sc[k] > m) { m = sc[k]; mi = c; }
        }
        #pragma unroll
        for (int o = 16; o; o >>= 1) {
            float om = __shfl_xor_sync(0xffffffffu, m, o);
            int   oi = __shfl_xor_sync(0xffffffffu, mi, o);
            if (om > m || (om == m && oi < mi)) { m = om; mi = oi; }
        }
        if (lane == 0) g_bp[t * S + s] = mi;
    }
}

// compose each chunk's backpointer map
__global__ void sv_link() {
    int b = blockIdx.x;
    if (b == 0) return;
    int cur = threadIdx.x;
    int tlo = b * CH;
    for (int t = tlo + CH - 2; t >= tlo - 1; --t)
        cur = g_bp[(t + 1) * S + cur];
    g_link[b][threadIdx.x] = cur;
}

__global__ void sv_back(float* __restrict__ out) {
    __shared__ float sm[8];
    __shared__ int   si[8];
    __shared__ int   sE[NB];
    const int tid = threadIdx.x, lane = tid & 31;

    const float* vlast = out + T + (size_t)(T - 1) * S;
    float m = vlast[tid]; int mi = tid;
    #pragma unroll
    for (int o = 16; o; o >>= 1) {
        float om = __shfl_xor_sync(0xffffffffu, m, o);
        int   oi = __shfl_xor_sync(0xffffffffu, mi, o);
        if (om > m || (om == m && oi < mi)) { m = om; mi = oi; }
    }
    if (lane == 0) { sm[tid >> 5] = m; si[tid >> 5] = mi; }
    __syncthreads();

    if (tid == 0) {
        m = sm[0]; mi = si[0];
        #pragma unroll
        for (int w = 1; w < 8; ++w)
            if (sm[w] > m || (sm[w] == m && si[w] < mi)) { m = sm[w]; mi = si[w]; }
        int e = mi;
        sE[NB - 1] = e;
        for (int b = NB - 1; b >= 1; --b) { e = g_link[b][e]; sE[b - 1] = e; }
    }
    __syncthreads();

    if (tid < NB) {
        int b = tid;
        int cur = sE[b];
        out[b * CH + CH - 1] = (float)cur;
        for (int t = b * CH + CH - 2; t >= b * CH; --t) {
            cur = g_bp[(t + 1) * S + cur];
            out[t] = (float)cur;
        }
    }
}

extern "C" void kernel_launch(void* const* d_in, const int* in_sizes, int n_in,
                              void* d_out, int out_size) {
    const float* pot = (const float*)d_in[0];
    float* out = (float*)d_out;

    // allow the 16-CTA non-portable cluster (idempotent, capture-legal)
    cudaFuncSetAttribute(sv_dp, cudaFuncAttributeNonPortableClusterSizeAllowed, 1);

    sv_dp<<<NCTA, 512>>>(pot, out);
    sv_bp<<<T - 1, 256>>>(pot, out);
    sv_link<<<NB, 256>>>();
    sv_back<<<1, 256>>>(out);
}